// round 11
// baseline (speedup 1.0000x reference)
#include <cuda_runtime.h>

#define NN   1024
#define BB   32
#define NBIN 1024

__device__ float    g_h[BB * NN * 6];      // layer-1 output (B, N, 6)
__device__ unsigned g_ready[BB];           // producer->consumer flags (consumers reset)

__device__ __forceinline__ int IDX(int i) { return i + (i >> 5); }
#define PADN (NN + (NN >> 5))   // 1056

// smem layout (bytes)
#define OFF_TAB   0
#define OFF_OFF   (10*PADN*4)              // tab:  float[10][PADN]
#define OFF_SCAT  (OFF_OFF + 10*32*4)      // off:  float[10][32]
#define OFF_CNT2  (OFF_SCAT + 5*PADN*4)    // scat: float[5][PADN]
#define OFF_CINC  (OFF_CNT2 + 36*NBIN)     // cnt2: u8[NBIN][36] (32 used, stride 36)
#define OFF_CEXC  (OFF_CINC + 4*NBIN)
#define OFF_WS    (OFF_CEXC + 4*NBIN)
#define OFF_RED   (OFF_WS + 128)
#define SMEM_BYTES (OFF_RED + 512)

// ---- all-read-all inclusive block scan, 1 value/thread, ONE internal barrier ----
__device__ __forceinline__ unsigned scanInclU32ara(unsigned v, unsigned* ws, int tid) {
    const int lane = tid & 31, wid = tid >> 5;
#pragma unroll
    for (int d = 1; d < 32; d <<= 1) {
        unsigned n = __shfl_up_sync(0xffffffffu, v, d);
        if (lane >= d) v += n;
    }
    if (lane == 31) ws[wid] = v;    // warp total
    __syncthreads();
    unsigned base = 0;
#pragma unroll
    for (int k = 0; k < 32; k++) {
        unsigned t = ws[k];         // broadcast LDS
        if (k < wid) base += t;
    }
    return base + v;
}

// ---- all-read-all block min/max, ONE internal barrier. red >= 64 floats ----
__device__ __forceinline__ float2 blockMinMax1(float v, float* red, int tid) {
    const int lane = tid & 31, wid = tid >> 5;
    float mx = v, mn = v;
#pragma unroll
    for (int d = 16; d >= 1; d >>= 1) {
        mx = fmaxf(mx, __shfl_xor_sync(0xffffffffu, mx, d));
        mn = fminf(mn, __shfl_xor_sync(0xffffffffu, mn, d));
    }
    if (lane == 0) { red[wid] = mx; red[32 + wid] = mn; }
    __syncthreads();
    mx = red[0]; mn = red[32];
#pragma unroll
    for (int k = 1; k < 32; k++) {
        mx = fmaxf(mx, red[k]);
        mn = fminf(mn, red[32 + k]);
    }
    return make_float2(mn, mx);
}

// ---- per-warp float prefix (fwd or reversed), no fixup pass ----
__device__ __forceinline__ void warpScanArrayF(
    const float* __restrict__ Barr, const float* __restrict__ wm,
    bool usew, bool powA, bool rev,
    float* __restrict__ tabrow, float* __restrict__ offrow, int lane)
{
    const int base = lane * 32;
    float acc = 0.f;
#pragma unroll 8
    for (int k = 0; k < 32; k++) {
        int pos = base + k;
        int id  = IDX(rev ? (NN - 1 - pos) : pos);
        float v = Barr[id];
        if (powA) { float b2 = v * v; v = b2 * b2 * v; }   // A = B^5
        if (usew) v *= wm[id];
        acc += v;
        tabrow[IDX(pos)] = acc;        // lane-chunk inclusive (by scan position)
    }
    float tot = acc, s = acc;
#pragma unroll
    for (int d = 1; d < 32; d <<= 1) {
        float n = __shfl_up_sync(0xffffffffu, s, d);
        if (lane >= d) s += n;
    }
    offrow[lane] = s - tot;            // exclusive chunk offset
}

__device__ __forceinline__ float tabQ(const float (*tab)[PADN],
                                      const float (*off)[32], int a, int pos) {
    return tab[a][IDX(pos)] + off[a][pos >> 5];
}

// ---------------------------------------------------------------------------
// 128 blocks: 0..95 layer-1 producers (head,batch); 96..127 layer-2 consumers.
// ---------------------------------------------------------------------------
__global__ void __launch_bounds__(1024, 1) gat_pc_kernel(
    const float* __restrict__ x,    // (B, N, 4)
    const float* __restrict__ W1,   // (3, 4, 2)
    const float* __restrict__ a1,   // (3, 4, 1)
    const float* __restrict__ W2,   // (1, 6, 4)
    const float* __restrict__ a2,   // (1, 8, 1)
    float* __restrict__ y)          // (B, N, 4)
{
    extern __shared__ unsigned char smraw[];
    float (*tab)[PADN]  = reinterpret_cast<float(*)[PADN]>(smraw + OFF_TAB);
    float (*off)[32]    = reinterpret_cast<float(*)[32]>(smraw + OFF_OFF);
    float (*scat)[PADN] = reinterpret_cast<float(*)[PADN]>(smraw + OFF_SCAT);
    unsigned char* cnt2 = smraw + OFF_CNT2;
    unsigned* cinc = reinterpret_cast<unsigned*>(smraw + OFF_CINC);
    unsigned* cexc = reinterpret_cast<unsigned*>(smraw + OFF_CEXC);
    unsigned* ws   = reinterpret_cast<unsigned*>(smraw + OFF_WS);
    float*    red  = reinterpret_cast<float*>(smraw + OFF_RED);

    const int bid  = blockIdx.x;
    const int tid  = threadIdx.x;
    const int lane = tid & 31, wid = tid >> 5;

    // zero cnt2 (9216 words); ordered before leader writes by minmax's barrier
    {
        unsigned* z = reinterpret_cast<unsigned*>(cnt2);
#pragma unroll
        for (int i = 0; i < 9; i++) z[tid + i * 1024] = 0u;
    }

    const bool isProd = (bid < 96);
    const int  b  = isProd ? (bid / 3) : (bid - 96);
    const int  hd = isProd ? (bid % 3) : 0;

    float ss, sd;
    float wh0, wh1;               // producer payload
    float wh[4];                  // consumer payload

    if (isProd) {
        float w[8];
#pragma unroll
        for (int i = 0; i < 8; i++) w[i] = W1[hd * 8 + i];
        float4 xv = reinterpret_cast<const float4*>(x)[b * NN + tid];
        wh0 = xv.x * w[0] + xv.y * w[2] + xv.z * w[4] + xv.w * w[6];
        wh1 = xv.x * w[1] + xv.y * w[3] + xv.z * w[5] + xv.w * w[7];
        ss = wh0 * a1[hd * 4 + 0] + wh1 * a1[hd * 4 + 1];
        sd = wh0 * a1[hd * 4 + 2] + wh1 * a1[hd * 4 + 3];
    } else {
        // preload all weights BEFORE the wait
        float w[24];
#pragma unroll
        for (int i = 0; i < 24; i++) w[i] = W2[i];
        float asv[4], adv[4];
#pragma unroll
        for (int o = 0; o < 4; o++) { asv[o] = a2[o]; adv[o] = a2[4 + o]; }

        if (tid == 0) {
            while (atomicAdd(&g_ready[b], 0u) < 3u) __nanosleep(32);
            __threadfence();         // acquire (cumulative)
        }
        __syncthreads();
        if (tid == 0) atomicExch(&g_ready[b], 0u);   // reset for next replay

        const float* hb = g_h + (size_t)(b * NN + tid) * 6;
        float2 h0 = *reinterpret_cast<const float2*>(hb);
        float2 h1 = *reinterpret_cast<const float2*>(hb + 2);
        float2 h2 = *reinterpret_cast<const float2*>(hb + 4);
        float xf[6] = {h0.x, h0.y, h1.x, h1.y, h2.x, h2.y};
#pragma unroll
        for (int o = 0; o < 4; o++) {
            float acc = 0.f;
#pragma unroll
            for (int f = 0; f < 6; f++) acc = fmaf(xf[f], w[f * 4 + o], acc);
            wh[o] = acc;
        }
        ss = 0.f; sd = 0.f;
#pragma unroll
        for (int o = 0; o < 4; o++) {
            ss = fmaf(wh[o], asv[o], ss);
            sd = fmaf(wh[o], adv[o], sd);
        }
    }

    float2 mm = blockMinMax1(sd, red, tid);
    const float mn = mm.x, M = mm.y;
    const float range = M - mn;
    const float scale = (range > 1e-30f) ? ((float)NBIN / range) : 0.0f;

    // ---- deterministic rank via match (no atomics) ----
    const int bj = min((int)((sd - mn) * scale), NBIN - 1);
    const unsigned mmask = __match_any_sync(0xffffffffu, bj);
    const unsigned rank  = __popc(mmask & ((1u << lane) - 1u));
    if (rank == 0)
        cnt2[bj * 36 + wid] = (unsigned char)__popc(mmask);
    __syncthreads();

    // cross-warp offset for own bin; bin totals; 1-barrier block scan
    unsigned wpre = 0;
    {
        const unsigned* rowj = reinterpret_cast<const unsigned*>(cnt2 + bj * 36);
        const int nw = wid >> 2, rb = (wid & 3) * 8;
#pragma unroll
        for (int k = 0; k < 8; k++) {
            unsigned word = rowj[k];
            unsigned msk = (k < nw) ? 0xffffffffu : ((k == nw) ? ((1u << rb) - 1u) : 0u);
            wpre = __dp4a(word & msk, 0x01010101u, wpre);
        }
    }
    {
        const unsigned* rowb = reinterpret_cast<const unsigned*>(cnt2 + tid * 36);
        unsigned tot = 0;
#pragma unroll
        for (int k = 0; k < 8; k++) tot = __dp4a(rowb[k], 0x01010101u, tot);
        unsigned ci = scanInclU32ara(tot, ws, tid);
        cinc[tid] = ci;
        cexc[tid] = ci - tot;
    }
    __syncthreads();

    // ---- scatter (counting-sort position, fully deterministic) ----
    const int ip = IDX((int)(cexc[bj] + wpre + rank));
    scat[0][ip] = __expf(0.2f * (sd - M));   // B; A = B^5
    if (isProd) {
        scat[1][ip] = wh0;
        scat[2][ip] = wh1;
    } else {
        scat[1][ip] = wh[0];
        scat[2][ip] = wh[1];
        scat[3][ip] = wh[2];
        scat[4][ip] = wh[3];
    }
    __syncthreads();

    // ---- warp-parallel float scans: fwd B-group, reversed A-group ----
    const int nArr = isProd ? 3 : 5;
    if (wid < 2 * nArr) {
        int grp = wid / nArr, c = wid % nArr;
        warpScanArrayF(scat[0], c ? scat[c] : scat[0], c != 0,
                       grp == 1, grp == 1, tab[wid], off[wid], lane);
    }
    __syncthreads();

    // ---- row phase ----
    const float u = ss + M;
    const float m = fmaxf(u, 0.2f * u);
    const float p = __expf(u - m);
    const float q = __expf(0.2f * u - m);
    const float t = -ss;
    const int bt = (t < mn) ? -1 : min((int)((t - mn) * scale), NBIN - 1);
    const int post = (bt >= 0) ? (int)cinc[bt] : 0;
    const int rpos = NN - 1 - post;          // reverse-scan position for suffix

    if (isProd) {
        float P0 = 0.f, P1 = 0.f, P2 = 0.f, S0 = 0.f, S1 = 0.f, S2 = 0.f;
        if (post > 0) {
            P0 = tabQ(tab, off, 0, post - 1);
            P1 = tabQ(tab, off, 1, post - 1);
            P2 = tabQ(tab, off, 2, post - 1);
        }
        if (post < NN) {
            S0 = tabQ(tab, off, 3, rpos);
            S1 = tabQ(tab, off, 4, rpos);
            S2 = tabQ(tab, off, 5, rpos);
        }
        const float denom = q * P0 + p * S0;
        const float inv = 1.0f / denom;
        float o0 = (q * P1 + p * S1) * inv;
        float o1 = (q * P2 + p * S2) * inv;
        o0 = (o0 > 0.f) ? o0 : expm1f(o0);
        o1 = (o1 > 0.f) ? o1 : expm1f(o1);

        float* dst = g_h + (size_t)(b * NN + tid) * 6 + hd * 2;
        dst[0] = o0;
        dst[1] = o1;

        __syncthreads();                 // all stores program-ordered before t0's fence
        if (tid == 0) {
            __threadfence();             // cumulative release
            atomicAdd(&g_ready[b], 1u);
        }
    } else {
        float P[5], S[5];
#pragma unroll
        for (int a = 0; a < 5; a++) { P[a] = 0.f; S[a] = 0.f; }
        if (post > 0) {
#pragma unroll
            for (int a = 0; a < 5; a++) P[a] = tabQ(tab, off, a, post - 1);
        }
        if (post < NN) {
#pragma unroll
            for (int a = 0; a < 5; a++) S[a] = tabQ(tab, off, 5 + a, rpos);
        }
        const float denom = q * P[0] + p * S[0];
        const float inv = 1.0f / denom;
        float o0 = (q * P[1] + p * S[1]) * inv;
        float o1 = (q * P[2] + p * S[2]) * inv;
        float o2 = (q * P[3] + p * S[3]) * inv;
        float o3 = (q * P[4] + p * S[4]) * inv;
        o0 = (o0 > 0.f) ? o0 : expm1f(o0);
        o1 = (o1 > 0.f) ? o1 : expm1f(o1);
        o2 = (o2 > 0.f) ? o2 : expm1f(o2);
        o3 = (o3 > 0.f) ? o3 : expm1f(o3);

        reinterpret_cast<float4*>(y)[b * NN + tid] = make_float4(o0, o1, o2, o3);
    }
}

extern "C" void kernel_launch(void* const* d_in, const int* in_sizes, int n_in,
                              void* d_out, int out_size)
{
    const float* x  = (const float*)d_in[0];
    const float* W1 = (const float*)d_in[1];
    const float* a1 = (const float*)d_in[2];
    const float* W2 = (const float*)d_in[3];
    const float* a2 = (const float*)d_in[4];
    float* y = (float*)d_out;

    static int configured = 0;
    if (!configured) {
        cudaFuncSetAttribute(gat_pc_kernel,
                             cudaFuncAttributeMaxDynamicSharedMemorySize, SMEM_BYTES);
        configured = 1;
    }

    gat_pc_kernel<<<96 + BB, 1024, SMEM_BYTES>>>(x, W1, a1, W2, a2, y);
}

// round 12
// speedup vs baseline: 1.1210x; 1.1210x over previous
#include <cuda_runtime.h>

#define NN   1024
#define BB   32
#define NBIN 1024

__device__ float    g_h[BB * NN * 6];      // layer-1 output (B, N, 6)
__device__ unsigned g_ready[BB];           // producer->consumer flags (consumers reset)

__device__ __forceinline__ int IDX(int i) { return i + (i >> 5); }
#define PADN (NN + (NN >> 5))   // 1056

// smem layout (bytes)
#define OFF_TAB   0
#define OFF_OFF2  (10*PADN*4)               // tab:  float[10][PADN]
#define OFF_HTOT  (OFF_OFF2 + 10*64*4)      // off2: float[10][64]
#define OFF_SCAT  (OFF_HTOT + 16*4)         // htot: float[10] (padded 16)
#define OFF_CNT2  (OFF_SCAT + 5*PADN*4)     // scat: float[5][PADN]
#define OFF_CINC  (OFF_CNT2 + 36*NBIN)      // cnt2: u8[NBIN][36] (32 used, stride 36)
#define OFF_CEXC  (OFF_CINC + 4*NBIN)
#define OFF_WS    (OFF_CEXC + 4*NBIN)
#define OFF_RED   (OFF_WS + 128)
#define SMEM_BYTES (OFF_RED + 512)

// ---- u32 inclusive block scan, 1 value/thread (2 internal barriers) ----
__device__ __forceinline__ unsigned scanInclU32(unsigned v, unsigned* ws, int tid) {
    const int lane = tid & 31, wid = tid >> 5;
#pragma unroll
    for (int d = 1; d < 32; d <<= 1) {
        unsigned n = __shfl_up_sync(0xffffffffu, v, d);
        if (lane >= d) v += n;
    }
    if (lane == 31) ws[wid] = v;
    __syncthreads();
    if (wid == 0) {
        unsigned w = ws[lane];
#pragma unroll
        for (int d = 1; d < 32; d <<= 1) {
            unsigned n = __shfl_up_sync(0xffffffffu, w, d);
            if (lane >= d) w += n;
        }
        ws[lane] = w;
    }
    __syncthreads();
    if (wid > 0) v += ws[wid - 1];
    return v;
}

// ---- 2-barrier block min/max. red holds >= 66 floats. returns (min,max) ----
__device__ __forceinline__ float2 blockMinMax2(float v, float* red, int tid) {
    const int lane = tid & 31, wid = tid >> 5;
    float mx = v, mn = v;
#pragma unroll
    for (int d = 16; d >= 1; d >>= 1) {
        mx = fmaxf(mx, __shfl_xor_sync(0xffffffffu, mx, d));
        mn = fminf(mn, __shfl_xor_sync(0xffffffffu, mn, d));
    }
    if (lane == 0) { red[wid] = mx; red[32 + wid] = mn; }
    __syncthreads();
    if (wid == 0) {
        mx = red[lane]; mn = red[32 + lane];
#pragma unroll
        for (int d = 16; d >= 1; d >>= 1) {
            mx = fmaxf(mx, __shfl_xor_sync(0xffffffffu, mx, d));
            mn = fminf(mn, __shfl_xor_sync(0xffffffffu, mn, d));
        }
        if (lane == 0) { red[64] = mn; red[65] = mx; }
    }
    __syncthreads();
    return make_float2(red[64], red[65]);
}

// ---- half-warp-range float prefix: this warp covers positions [half*512, +512),
//      16 elems/lane. off2row gets 64 chunk offsets (local to its half);
//      h=0 warp stores its total to *htot. ----
__device__ __forceinline__ void warpScanArrayF2(
    const float* __restrict__ Barr, const float* __restrict__ wm,
    bool usew, bool powA, bool rev, int half,
    float* __restrict__ tabrow, float* __restrict__ off2row,
    float* __restrict__ htot, int lane)
{
    const int base = half * 512 + lane * 16;
    float acc = 0.f;
#pragma unroll
    for (int k = 0; k < 16; k++) {
        int pos = base + k;
        int id  = IDX(rev ? (NN - 1 - pos) : pos);
        float v = Barr[id];
        if (powA) { float b2 = v * v; v = b2 * b2 * v; }   // A = B^5
        if (usew) v *= wm[id];
        acc += v;
        tabrow[IDX(pos)] = acc;        // chunk-local inclusive (by scan position)
    }
    float tot = acc, s = acc;
#pragma unroll
    for (int d = 1; d < 32; d <<= 1) {
        float n = __shfl_up_sync(0xffffffffu, s, d);
        if (lane >= d) s += n;
    }
    off2row[half * 32 + lane] = s - tot;   // exclusive chunk offset (half-local)
    if (half == 0 && lane == 31) *htot = s;
}

// inclusive prefix query at scan position pos (>=0)
__device__ __forceinline__ float tabQ(const float (*tab)[PADN],
                                      const float (*off2)[64],
                                      const float* htot, int a, int pos) {
    int ch = pos >> 4;
    float v = tab[a][IDX(pos)] + off2[a][ch];
    if (ch >= 32) v += htot[a];
    return v;
}

// ---------------------------------------------------------------------------
// 128 blocks: 0..95 layer-1 producers (head,batch); 96..127 layer-2 consumers.
// ---------------------------------------------------------------------------
__global__ void __launch_bounds__(1024, 1) gat_pc_kernel(
    const float* __restrict__ x,    // (B, N, 4)
    const float* __restrict__ W1,   // (3, 4, 2)
    const float* __restrict__ a1,   // (3, 4, 1)
    const float* __restrict__ W2,   // (1, 6, 4)
    const float* __restrict__ a2,   // (1, 8, 1)
    float* __restrict__ y)          // (B, N, 4)
{
    extern __shared__ unsigned char smraw[];
    float (*tab)[PADN]  = reinterpret_cast<float(*)[PADN]>(smraw + OFF_TAB);
    float (*off2)[64]   = reinterpret_cast<float(*)[64]>(smraw + OFF_OFF2);
    float* htot         = reinterpret_cast<float*>(smraw + OFF_HTOT);
    float (*scat)[PADN] = reinterpret_cast<float(*)[PADN]>(smraw + OFF_SCAT);
    unsigned char* cnt2 = smraw + OFF_CNT2;
    unsigned* cinc = reinterpret_cast<unsigned*>(smraw + OFF_CINC);
    unsigned* cexc = reinterpret_cast<unsigned*>(smraw + OFF_CEXC);
    unsigned* ws   = reinterpret_cast<unsigned*>(smraw + OFF_WS);
    float*    red  = reinterpret_cast<float*>(smraw + OFF_RED);

    const int bid  = blockIdx.x;
    const int tid  = threadIdx.x;
    const int lane = tid & 31, wid = tid >> 5;

    // zero cnt2 (9216 words); ordered before leader writes by minmax barriers
    {
        unsigned* z = reinterpret_cast<unsigned*>(cnt2);
#pragma unroll
        for (int i = 0; i < 9; i++) z[tid + i * 1024] = 0u;
    }

    const bool isProd = (bid < 96);
    const int  b  = isProd ? (bid / 3) : (bid - 96);
    const int  hd = isProd ? (bid % 3) : 0;

    float ss, sd;
    float wh0, wh1;               // producer payload
    float wh[4];                  // consumer payload

    if (isProd) {
        float w[8];
#pragma unroll
        for (int i = 0; i < 8; i++) w[i] = W1[hd * 8 + i];
        float4 xv = reinterpret_cast<const float4*>(x)[b * NN + tid];
        wh0 = xv.x * w[0] + xv.y * w[2] + xv.z * w[4] + xv.w * w[6];
        wh1 = xv.x * w[1] + xv.y * w[3] + xv.z * w[5] + xv.w * w[7];
        ss = wh0 * a1[hd * 4 + 0] + wh1 * a1[hd * 4 + 1];
        sd = wh0 * a1[hd * 4 + 2] + wh1 * a1[hd * 4 + 3];
    } else {
        // preload all weights BEFORE the wait
        float w[24];
#pragma unroll
        for (int i = 0; i < 24; i++) w[i] = W2[i];
        float asv[4], adv[4];
#pragma unroll
        for (int o = 0; o < 4; o++) { asv[o] = a2[o]; adv[o] = a2[4 + o]; }

        if (tid == 0) {
            while (atomicAdd(&g_ready[b], 0u) < 3u) __nanosleep(32);
            __threadfence();         // acquire (cumulative)
        }
        __syncthreads();
        if (tid == 0) atomicExch(&g_ready[b], 0u);   // reset for next replay

        const float* hb = g_h + (size_t)(b * NN + tid) * 6;
        float2 h0 = *reinterpret_cast<const float2*>(hb);
        float2 h1 = *reinterpret_cast<const float2*>(hb + 2);
        float2 h2 = *reinterpret_cast<const float2*>(hb + 4);
        float xf[6] = {h0.x, h0.y, h1.x, h1.y, h2.x, h2.y};
#pragma unroll
        for (int o = 0; o < 4; o++) {
            float acc = 0.f;
#pragma unroll
            for (int f = 0; f < 6; f++) acc = fmaf(xf[f], w[f * 4 + o], acc);
            wh[o] = acc;
        }
        ss = 0.f; sd = 0.f;
#pragma unroll
        for (int o = 0; o < 4; o++) {
            ss = fmaf(wh[o], asv[o], ss);
            sd = fmaf(wh[o], adv[o], sd);
        }
    }

    float2 mm = blockMinMax2(sd, red, tid);
    const float mn = mm.x, M = mm.y;
    const float range = M - mn;
    const float scale = (range > 1e-30f) ? ((float)NBIN / range) : 0.0f;

    // ---- deterministic rank via match (no atomics) ----
    const int bj = min((int)((sd - mn) * scale), NBIN - 1);
    const unsigned mmask = __match_any_sync(0xffffffffu, bj);
    const unsigned rank  = __popc(mmask & ((1u << lane) - 1u));
    if (rank == 0)
        cnt2[bj * 36 + wid] = (unsigned char)__popc(mmask);
    __syncthreads();

    // cross-warp offset for own bin; bin totals; block scan
    unsigned wpre = 0;
    {
        const unsigned* rowj = reinterpret_cast<const unsigned*>(cnt2 + bj * 36);
        const int nw = wid >> 2, rb = (wid & 3) * 8;
#pragma unroll
        for (int k = 0; k < 8; k++) {
            unsigned word = rowj[k];
            unsigned msk = (k < nw) ? 0xffffffffu : ((k == nw) ? ((1u << rb) - 1u) : 0u);
            wpre = __dp4a(word & msk, 0x01010101u, wpre);
        }
    }
    {
        const unsigned* rowb = reinterpret_cast<const unsigned*>(cnt2 + tid * 36);
        unsigned tot = 0;
#pragma unroll
        for (int k = 0; k < 8; k++) tot = __dp4a(rowb[k], 0x01010101u, tot);
        unsigned ci = scanInclU32(tot, ws, tid);
        cinc[tid] = ci;
        cexc[tid] = ci - tot;
    }
    __syncthreads();

    // ---- scatter (counting-sort position, fully deterministic) ----
    const int ip = IDX((int)(cexc[bj] + wpre + rank));
    scat[0][ip] = __expf(0.2f * (sd - M));   // B; A = B^5
    if (isProd) {
        scat[1][ip] = wh0;
        scat[2][ip] = wh1;
    } else {
        scat[1][ip] = wh[0];
        scat[2][ip] = wh[1];
        scat[3][ip] = wh[2];
        scat[4][ip] = wh[3];
    }

    // ---- hoist row-phase scalars (MUFU latency overlaps scan phase) ----
    const float u = ss + M;
    const float m = fmaxf(u, 0.2f * u);
    const float p = __expf(u - m);
    const float q = __expf(0.2f * u - m);
    const float t = -ss;
    const int bt = (t < mn) ? -1 : min((int)((t - mn) * scale), NBIN - 1);
    const int post = (bt >= 0) ? (int)cinc[bt] : 0;
    const int rpos = NN - 1 - post;          // reverse-scan position for suffix
    __syncthreads();

    // ---- warp-parallel float scans, 2 warps per array ----
    const int nArr = isProd ? 3 : 5;
    if (wid < 4 * nArr) {
        const int a    = wid >> 1;            // array id 0..2*nArr-1
        const int half = wid & 1;
        const int grp  = a / nArr;            // 0 => B fwd, 1 => A rev
        const int c    = a % nArr;
        warpScanArrayF2(scat[0], c ? scat[c] : scat[0], c != 0,
                        grp == 1, grp == 1, half,
                        tab[a], off2[a], &htot[a], lane);
    }
    __syncthreads();

    // ---- row phase ----
    if (isProd) {
        float P0 = 0.f, P1 = 0.f, P2 = 0.f, S0 = 0.f, S1 = 0.f, S2 = 0.f;
        if (post > 0) {
            P0 = tabQ(tab, off2, htot, 0, post - 1);
            P1 = tabQ(tab, off2, htot, 1, post - 1);
            P2 = tabQ(tab, off2, htot, 2, post - 1);
        }
        if (post < NN) {
            S0 = tabQ(tab, off2, htot, 3, rpos);
            S1 = tabQ(tab, off2, htot, 4, rpos);
            S2 = tabQ(tab, off2, htot, 5, rpos);
        }
        const float denom = q * P0 + p * S0;
        const float inv = 1.0f / denom;
        float o0 = (q * P1 + p * S1) * inv;
        float o1 = (q * P2 + p * S2) * inv;
        o0 = (o0 > 0.f) ? o0 : expm1f(o0);
        o1 = (o1 > 0.f) ? o1 : expm1f(o1);

        *reinterpret_cast<float2*>(g_h + (size_t)(b * NN + tid) * 6 + hd * 2)
            = make_float2(o0, o1);

        __syncthreads();                 // all stores ordered before t0's fence
        if (tid == 0) {
            __threadfence();             // cumulative release
            atomicAdd(&g_ready[b], 1u);
        }
    } else {
        float P[5], S[5];
#pragma unroll
        for (int a = 0; a < 5; a++) { P[a] = 0.f; S[a] = 0.f; }
        if (post > 0) {
#pragma unroll
            for (int a = 0; a < 5; a++) P[a] = tabQ(tab, off2, htot, a, post - 1);
        }
        if (post < NN) {
#pragma unroll
            for (int a = 0; a < 5; a++) S[a] = tabQ(tab, off2, htot, 5 + a, rpos);
        }
        const float denom = q * P[0] + p * S[0];
        const float inv = 1.0f / denom;
        float o0 = (q * P[1] + p * S[1]) * inv;
        float o1 = (q * P[2] + p * S[2]) * inv;
        float o2 = (q * P[3] + p * S[3]) * inv;
        float o3 = (q * P[4] + p * S[4]) * inv;
        o0 = (o0 > 0.f) ? o0 : expm1f(o0);
        o1 = (o1 > 0.f) ? o1 : expm1f(o1);
        o2 = (o2 > 0.f) ? o2 : expm1f(o2);
        o3 = (o3 > 0.f) ? o3 : expm1f(o3);

        reinterpret_cast<float4*>(y)[b * NN + tid] = make_float4(o0, o1, o2, o3);
    }
}

extern "C" void kernel_launch(void* const* d_in, const int* in_sizes, int n_in,
                              void* d_out, int out_size)
{
    const float* x  = (const float*)d_in[0];
    const float* W1 = (const float*)d_in[1];
    const float* a1 = (const float*)d_in[2];
    const float* W2 = (const float*)d_in[3];
    const float* a2 = (const float*)d_in[4];
    float* y = (float*)d_out;

    static int configured = 0;
    if (!configured) {
        cudaFuncSetAttribute(gat_pc_kernel,
                             cudaFuncAttributeMaxDynamicSharedMemorySize, SMEM_BYTES);
        configured = 1;
    }

    gat_pc_kernel<<<96 + BB, 1024, SMEM_BYTES>>>(x, W1, a1, W2, a2, y);
}

// round 13
// speedup vs baseline: 1.1402x; 1.0170x over previous
#include <cuda_runtime.h>

#define NN   1024
#define BB   32
#define NBIN 1024

__device__ float    g_h[BB * NN * 6];      // layer-1 output (B, N, 6)
__device__ unsigned g_ready[BB];           // producer->consumer flags (consumers reset)

__device__ __forceinline__ int IDX(int i) { return i + (i >> 5); }
#define PADN (NN + (NN >> 5))   // 1056

// smem layout (bytes)
#define OFF_TAB   0
#define OFF_OFF2  (10*PADN*4)               // tab:  float[10][PADN]
#define OFF_HTOT  (OFF_OFF2 + 10*64*4)      // off2: float[10][64]
#define OFF_SCAT  (OFF_HTOT + 16*4)         // htot: float[10] (padded 16)
#define OFF_CNT2  (OFF_SCAT + 10*PADN*4)    // scat: float[10][PADN] (product arrays)
#define OFF_CINC  (OFF_CNT2 + 36*NBIN)      // cnt2: u8[NBIN][36] (32 used, stride 36)
#define OFF_CEXC  (OFF_CINC + 4*NBIN)
#define OFF_WS    (OFF_CEXC + 4*NBIN)
#define OFF_RED   (OFF_WS + 128)
#define SMEM_BYTES (OFF_RED + 512)

// ---- 1-barrier u32 inclusive block scan: warp leaders deposit, every warp
//      redundantly shfl-scans the 32 totals (log-depth) ----
__device__ __forceinline__ unsigned scanInclU32b(unsigned v, unsigned* ws, int tid) {
    const int lane = tid & 31, wid = tid >> 5;
#pragma unroll
    for (int d = 1; d < 32; d <<= 1) {
        unsigned n = __shfl_up_sync(0xffffffffu, v, d);
        if (lane >= d) v += n;
    }
    if (lane == 31) ws[wid] = v;
    __syncthreads();
    unsigned t = ws[lane];
#pragma unroll
    for (int d = 1; d < 32; d <<= 1) {
        unsigned n = __shfl_up_sync(0xffffffffu, t, d);
        if (lane >= d) t += n;
    }
    unsigned base = __shfl_sync(0xffffffffu, t, (wid > 0) ? (wid - 1) : 0);
    return ((wid > 0) ? base : 0u) + v;
}

// ---- 1-barrier block min/max: every warp redundantly shfl-reduces the 32
//      leader partials. red >= 64 floats. returns (min,max) on all threads ----
__device__ __forceinline__ float2 blockMinMax1(float v, float* red, int tid) {
    const int lane = tid & 31, wid = tid >> 5;
    float mx = v, mn = v;
#pragma unroll
    for (int d = 16; d >= 1; d >>= 1) {
        mx = fmaxf(mx, __shfl_xor_sync(0xffffffffu, mx, d));
        mn = fminf(mn, __shfl_xor_sync(0xffffffffu, mn, d));
    }
    if (lane == 0) { red[wid] = mx; red[32 + wid] = mn; }
    __syncthreads();
    mx = red[lane]; mn = red[32 + lane];
#pragma unroll
    for (int d = 16; d >= 1; d >>= 1) {
        mx = fmaxf(mx, __shfl_xor_sync(0xffffffffu, mx, d));
        mn = fminf(mn, __shfl_xor_sync(0xffffffffu, mn, d));
    }
    return make_float2(mn, mx);
}

// ---- half-range float prefix over ONE product array (fwd or reversed):
//      warp covers positions [half*512, +512), 16 elems/lane ----
__device__ __forceinline__ void warpScanArrayF3(
    const float* __restrict__ src, bool rev, int half,
    float* __restrict__ tabrow, float* __restrict__ off2row,
    float* __restrict__ htot, int lane)
{
    const int base = half * 512 + lane * 16;
    float acc = 0.f;
#pragma unroll
    for (int k = 0; k < 16; k++) {
        int pos = base + k;
        int id  = IDX(rev ? (NN - 1 - pos) : pos);
        acc += src[id];
        tabrow[IDX(pos)] = acc;        // chunk-local inclusive (by scan position)
    }
    float tot = acc, s = acc;
#pragma unroll
    for (int d = 1; d < 32; d <<= 1) {
        float n = __shfl_up_sync(0xffffffffu, s, d);
        if (lane >= d) s += n;
    }
    off2row[half * 32 + lane] = s - tot;   // exclusive chunk offset (half-local)
    if (half == 0 && lane == 31) *htot = s;
}

// inclusive prefix query at scan position pos (>=0)
__device__ __forceinline__ float tabQ(const float (*tab)[PADN],
                                      const float (*off2)[64],
                                      const float* htot, int a, int pos) {
    int ch = pos >> 4;
    float v = tab[a][IDX(pos)] + off2[a][ch];
    if (ch >= 32) v += htot[a];
    return v;
}

// ---------------------------------------------------------------------------
// 128 blocks: 0..95 layer-1 producers (head,batch); 96..127 layer-2 consumers.
// ---------------------------------------------------------------------------
__global__ void __launch_bounds__(1024, 1) gat_pc_kernel(
    const float* __restrict__ x,    // (B, N, 4)
    const float* __restrict__ W1,   // (3, 4, 2)
    const float* __restrict__ a1,   // (3, 4, 1)
    const float* __restrict__ W2,   // (1, 6, 4)
    const float* __restrict__ a2,   // (1, 8, 1)
    float* __restrict__ y)          // (B, N, 4)
{
    extern __shared__ unsigned char smraw[];
    float (*tab)[PADN]  = reinterpret_cast<float(*)[PADN]>(smraw + OFF_TAB);
    float (*off2)[64]   = reinterpret_cast<float(*)[64]>(smraw + OFF_OFF2);
    float* htot         = reinterpret_cast<float*>(smraw + OFF_HTOT);
    float (*scat)[PADN] = reinterpret_cast<float(*)[PADN]>(smraw + OFF_SCAT);
    unsigned char* cnt2 = smraw + OFF_CNT2;
    unsigned* cinc = reinterpret_cast<unsigned*>(smraw + OFF_CINC);
    unsigned* cexc = reinterpret_cast<unsigned*>(smraw + OFF_CEXC);
    unsigned* ws   = reinterpret_cast<unsigned*>(smraw + OFF_WS);
    float*    red  = reinterpret_cast<float*>(smraw + OFF_RED);

    const int bid  = blockIdx.x;
    const int tid  = threadIdx.x;
    const int lane = tid & 31, wid = tid >> 5;

    // zero cnt2 (9216 words); ordered before leader writes by minmax barrier
    {
        unsigned* z = reinterpret_cast<unsigned*>(cnt2);
#pragma unroll
        for (int i = 0; i < 9; i++) z[tid + i * 1024] = 0u;
    }

    const bool isProd = (bid < 96);
    const int  b  = isProd ? (bid / 3) : (bid - 96);
    const int  hd = isProd ? (bid % 3) : 0;

    float ss, sd;
    float wh0, wh1;               // producer payload
    float wh[4];                  // consumer payload

    if (isProd) {
        float w[8];
#pragma unroll
        for (int i = 0; i < 8; i++) w[i] = W1[hd * 8 + i];
        float4 xv = reinterpret_cast<const float4*>(x)[b * NN + tid];
        wh0 = xv.x * w[0] + xv.y * w[2] + xv.z * w[4] + xv.w * w[6];
        wh1 = xv.x * w[1] + xv.y * w[3] + xv.z * w[5] + xv.w * w[7];
        ss = wh0 * a1[hd * 4 + 0] + wh1 * a1[hd * 4 + 1];
        sd = wh0 * a1[hd * 4 + 2] + wh1 * a1[hd * 4 + 3];
    } else {
        // preload all weights BEFORE the wait
        float w[24];
#pragma unroll
        for (int i = 0; i < 24; i++) w[i] = W2[i];
        float asv[4], adv[4];
#pragma unroll
        for (int o = 0; o < 4; o++) { asv[o] = a2[o]; adv[o] = a2[4 + o]; }

        if (tid == 0) {
            while (atomicAdd(&g_ready[b], 0u) < 3u) __nanosleep(32);
            __threadfence();         // acquire (cumulative)
        }
        __syncthreads();
        if (tid == 0) atomicExch(&g_ready[b], 0u);   // reset for next replay

        const float* hb = g_h + (size_t)(b * NN + tid) * 6;
        float2 h0 = *reinterpret_cast<const float2*>(hb);
        float2 h1 = *reinterpret_cast<const float2*>(hb + 2);
        float2 h2 = *reinterpret_cast<const float2*>(hb + 4);
        float xf[6] = {h0.x, h0.y, h1.x, h1.y, h2.x, h2.y};
#pragma unroll
        for (int o = 0; o < 4; o++) {
            float acc = 0.f;
#pragma unroll
            for (int f = 0; f < 6; f++) acc = fmaf(xf[f], w[f * 4 + o], acc);
            wh[o] = acc;
        }
        ss = 0.f; sd = 0.f;
#pragma unroll
        for (int o = 0; o < 4; o++) {
            ss = fmaf(wh[o], asv[o], ss);
            sd = fmaf(wh[o], adv[o], sd);
        }
    }

    float2 mm = blockMinMax1(sd, red, tid);
    const float mn = mm.x, M = mm.y;
    const float range = M - mn;
    const float scale = (range > 1e-30f) ? ((float)NBIN / range) : 0.0f;

    // ---- deterministic rank via match (no atomics) ----
    const int bj = min((int)((sd - mn) * scale), NBIN - 1);
    const unsigned mmask = __match_any_sync(0xffffffffu, bj);
    const unsigned rank  = __popc(mmask & ((1u << lane) - 1u));
    if (rank == 0)
        cnt2[bj * 36 + wid] = (unsigned char)__popc(mmask);
    __syncthreads();

    // cross-warp offset for own bin; bin totals; 1-barrier block scan
    unsigned wpre = 0;
    {
        const unsigned* rowj = reinterpret_cast<const unsigned*>(cnt2 + bj * 36);
        const int nw = wid >> 2, rb = (wid & 3) * 8;
#pragma unroll
        for (int k = 0; k < 8; k++) {
            unsigned word = rowj[k];
            unsigned msk = (k < nw) ? 0xffffffffu : ((k == nw) ? ((1u << rb) - 1u) : 0u);
            wpre = __dp4a(word & msk, 0x01010101u, wpre);
        }
    }
    {
        const unsigned* rowb = reinterpret_cast<const unsigned*>(cnt2 + tid * 36);
        unsigned tot = 0;
#pragma unroll
        for (int k = 0; k < 8; k++) tot = __dp4a(rowb[k], 0x01010101u, tot);
        unsigned ci = scanInclU32b(tot, ws, tid);
        cinc[tid] = ci;
        cexc[tid] = ci - tot;
    }
    __syncthreads();

    // ---- scatter final PRODUCT arrays (counting-sort position, deterministic) ----
    const int ip = IDX((int)(cexc[bj] + wpre + rank));
    {
        float Bv = __expf(0.2f * (sd - M));
        float b2 = Bv * Bv;
        float Av = b2 * b2 * Bv;             // A = B^5
        if (isProd) {
            scat[0][ip] = Bv;
            scat[1][ip] = Bv * wh0;
            scat[2][ip] = Bv * wh1;
            scat[3][ip] = Av;
            scat[4][ip] = Av * wh0;
            scat[5][ip] = Av * wh1;
        } else {
            scat[0][ip] = Bv;
            scat[1][ip] = Bv * wh[0];
            scat[2][ip] = Bv * wh[1];
            scat[3][ip] = Bv * wh[2];
            scat[4][ip] = Bv * wh[3];
            scat[5][ip] = Av;
            scat[6][ip] = Av * wh[0];
            scat[7][ip] = Av * wh[1];
            scat[8][ip] = Av * wh[2];
            scat[9][ip] = Av * wh[3];
        }
    }

    // ---- hoist row-phase scalars (MUFU latency overlaps scan phase) ----
    const float u = ss + M;
    const float m = fmaxf(u, 0.2f * u);
    const float p = __expf(u - m);
    const float q = __expf(0.2f * u - m);
    const float t = -ss;
    const int bt = (t < mn) ? -1 : min((int)((t - mn) * scale), NBIN - 1);
    const int post = (bt >= 0) ? (int)cinc[bt] : 0;
    const int rpos = NN - 1 - post;          // reverse-scan position for suffix
    __syncthreads();

    // ---- warp-parallel float scans, 2 warps per array, 1 array per warp ----
    const int nArr = isProd ? 3 : 5;
    if (wid < 4 * nArr) {
        const int a    = wid >> 1;            // array id 0..2*nArr-1
        const int half = wid & 1;
        warpScanArrayF3(scat[a], a >= nArr, half,
                        tab[a], off2[a], &htot[a], lane);
    }
    __syncthreads();

    // ---- row phase ----
    if (isProd) {
        float P0 = 0.f, P1 = 0.f, P2 = 0.f, S0 = 0.f, S1 = 0.f, S2 = 0.f;
        if (post > 0) {
            P0 = tabQ(tab, off2, htot, 0, post - 1);
            P1 = tabQ(tab, off2, htot, 1, post - 1);
            P2 = tabQ(tab, off2, htot, 2, post - 1);
        }
        if (post < NN) {
            S0 = tabQ(tab, off2, htot, 3, rpos);
            S1 = tabQ(tab, off2, htot, 4, rpos);
            S2 = tabQ(tab, off2, htot, 5, rpos);
        }
        const float denom = q * P0 + p * S0;
        const float inv = 1.0f / denom;
        float o0 = (q * P1 + p * S1) * inv;
        float o1 = (q * P2 + p * S2) * inv;
        o0 = (o0 > 0.f) ? o0 : expm1f(o0);
        o1 = (o1 > 0.f) ? o1 : expm1f(o1);

        *reinterpret_cast<float2*>(g_h + (size_t)(b * NN + tid) * 6 + hd * 2)
            = make_float2(o0, o1);

        __syncthreads();                 // all stores ordered before t0's fence
        if (tid == 0) {
            __threadfence();             // cumulative release
            atomicAdd(&g_ready[b], 1u);
        }
    } else {
        float P[5], S[5];
#pragma unroll
        for (int a = 0; a < 5; a++) { P[a] = 0.f; S[a] = 0.f; }
        if (post > 0) {
#pragma unroll
            for (int a = 0; a < 5; a++) P[a] = tabQ(tab, off2, htot, a, post - 1);
        }
        if (post < NN) {
#pragma unroll
            for (int a = 0; a < 5; a++) S[a] = tabQ(tab, off2, htot, 5 + a, rpos);
        }
        const float denom = q * P[0] + p * S[0];
        const float inv = 1.0f / denom;
        float o0 = (q * P[1] + p * S[1]) * inv;
        float o1 = (q * P[2] + p * S[2]) * inv;
        float o2 = (q * P[3] + p * S[3]) * inv;
        float o3 = (q * P[4] + p * S[4]) * inv;
        o0 = (o0 > 0.f) ? o0 : expm1f(o0);
        o1 = (o1 > 0.f) ? o1 : expm1f(o1);
        o2 = (o2 > 0.f) ? o2 : expm1f(o2);
        o3 = (o3 > 0.f) ? o3 : expm1f(o3);

        reinterpret_cast<float4*>(y)[b * NN + tid] = make_float4(o0, o1, o2, o3);
    }
}

extern "C" void kernel_launch(void* const* d_in, const int* in_sizes, int n_in,
                              void* d_out, int out_size)
{
    const float* x  = (const float*)d_in[0];
    const float* W1 = (const float*)d_in[1];
    const float* a1 = (const float*)d_in[2];
    const float* W2 = (const float*)d_in[3];
    const float* a2 = (const float*)d_in[4];
    float* y = (float*)d_out;

    static int configured = 0;
    if (!configured) {
        cudaFuncSetAttribute(gat_pc_kernel,
                             cudaFuncAttributeMaxDynamicSharedMemorySize, SMEM_BYTES);
        configured = 1;
    }

    gat_pc_kernel<<<96 + BB, 1024, SMEM_BYTES>>>(x, W1, a1, W2, a2, y);
}